// round 1
// baseline (speedup 1.0000x reference)
#include <cuda_runtime.h>
#include <math.h>

// Fixed problem shape (ReRanker reference): B=256, C=128, D=1024, fp32.
#define BB 256
#define CC 128
#define DD 1024
#define NWARPS 8          // 256 threads
#define EPS 1e-8f

__global__ __launch_bounds__(256, 2) void reranker_kernel(
    const float* __restrict__ doc,
    const float* __restrict__ summ,
    const float* __restrict__ cand,
    float* __restrict__ out)
{
    const int b   = blockIdx.x;
    const int tid = threadIdx.x;
    const int w   = tid >> 5;
    const int l   = tid & 31;

    __shared__ float4 docs[DD / 4];              // 4 KB
    __shared__ float4 sums[DD / 4];              // 4 KB
    __shared__ float4 Spriv[NWARPS][DD / 4];     // 32 KB (warp-private S, then S final in Spriv[0])
    __shared__ float  rcn_s[CC];                 // 512 B
    __shared__ float  red[3][NWARPS];
    __shared__ float  wsum[NWARPS];
    __shared__ float  sc_rdn, sc_rsn;

    // ---- load doc/summary rows, compute dn, sn, doc·summary ----
    const float4* docg = (const float4*)(doc  + (size_t)b * DD);
    const float4* sumg = (const float4*)(summ + (size_t)b * DD);
    float4 dv = docg[tid];
    float4 sv = sumg[tid];
    docs[tid] = dv;
    sums[tid] = sv;

    float pdd = dv.x*dv.x + dv.y*dv.y + dv.z*dv.z + dv.w*dv.w;
    float pss = sv.x*sv.x + sv.y*sv.y + sv.z*sv.z + sv.w*sv.w;
    float pds = dv.x*sv.x + dv.y*sv.y + dv.z*sv.z + dv.w*sv.w;
    #pragma unroll
    for (int o = 16; o; o >>= 1) {
        pdd += __shfl_xor_sync(0xffffffffu, pdd, o);
        pss += __shfl_xor_sync(0xffffffffu, pss, o);
        pds += __shfl_xor_sync(0xffffffffu, pds, o);
    }
    if (l == 0) { red[0][w] = pdd; red[1][w] = pss; red[2][w] = pds; }
    __syncthreads();
    if (tid == 0) {
        float dd = 0.f, ss = 0.f, ds = 0.f;
        #pragma unroll
        for (int i = 0; i < NWARPS; i++) { dd += red[0][i]; ss += red[1][i]; ds += red[2][i]; }
        float dn = fmaxf(sqrtf(dd), EPS);
        float sn = fmaxf(sqrtf(ss), EPS);
        sc_rdn = 1.0f / dn;
        sc_rsn = 1.0f / sn;
        out[2 * BB * CC + b] = ds / (dn * sn);          // summary_score[b]
    }
    __syncthreads();
    const float rdn = sc_rdn;
    const float rsn = sc_rsn;

    // ---- Pass A: norms, outer score, summary·cand, accumulate S in registers ----
    const float4* cb = (const float4*)(cand + (size_t)b * CC * DD);
    float4 Sacc[8];
    #pragma unroll
    for (int i = 0; i < 8; i++) Sacc[i] = make_float4(0.f, 0.f, 0.f, 0.f);
    float scpart = 0.f;

    for (int r = w; r < CC; r += NWARPS) {
        const float4* rowp = cb + (size_t)r * (DD / 4);
        float4 v[8];
        #pragma unroll
        for (int i = 0; i < 8; i++) v[i] = rowp[i * 32 + l];

        float ss = 0.f, dd = 0.f, sd = 0.f;
        #pragma unroll
        for (int i = 0; i < 8; i++) {
            float4 a  = v[i];
            float4 d4 = docs[i * 32 + l];
            float4 s4 = sums[i * 32 + l];
            ss = fmaf(a.x, a.x, ss); ss = fmaf(a.y, a.y, ss);
            ss = fmaf(a.z, a.z, ss); ss = fmaf(a.w, a.w, ss);
            dd = fmaf(a.x, d4.x, dd); dd = fmaf(a.y, d4.y, dd);
            dd = fmaf(a.z, d4.z, dd); dd = fmaf(a.w, d4.w, dd);
            sd = fmaf(a.x, s4.x, sd); sd = fmaf(a.y, s4.y, sd);
            sd = fmaf(a.z, s4.z, sd); sd = fmaf(a.w, s4.w, sd);
        }
        #pragma unroll
        for (int o = 16; o; o >>= 1) {
            ss += __shfl_xor_sync(0xffffffffu, ss, o);
            dd += __shfl_xor_sync(0xffffffffu, dd, o);
            sd += __shfl_xor_sync(0xffffffffu, sd, o);
        }
        float cn  = fmaxf(sqrtf(ss), EPS);
        float rcn = 1.0f / cn;
        if (l == 0) {
            out[b * CC + r] = dd * rcn * rdn;           // outer_score[b,r]
            rcn_s[r] = rcn;
        }
        scpart = fmaf(sd, rcn, scpart);                  // identical across lanes
        #pragma unroll
        for (int i = 0; i < 8; i++) {
            Sacc[i].x = fmaf(v[i].x, rcn, Sacc[i].x);
            Sacc[i].y = fmaf(v[i].y, rcn, Sacc[i].y);
            Sacc[i].z = fmaf(v[i].z, rcn, Sacc[i].z);
            Sacc[i].w = fmaf(v[i].w, rcn, Sacc[i].w);
        }
    }
    #pragma unroll
    for (int i = 0; i < 8; i++) Spriv[w][i * 32 + l] = Sacc[i];
    if (l == 0) wsum[w] = scpart;
    __syncthreads();

    // ---- reduce warp-private S copies; finish summary_avg ----
    {
        float4 st = Spriv[0][tid];
        #pragma unroll
        for (int ww = 1; ww < NWARPS; ww++) {
            float4 t = Spriv[ww][tid];
            st.x += t.x; st.y += t.y; st.z += t.z; st.w += t.w;
        }
        Spriv[0][tid] = st;
    }
    if (tid == 0) {
        float acc = 0.f;
        #pragma unroll
        for (int i = 0; i < NWARPS; i++) acc += wsum[i];
        out[2 * BB * CC + BB + b] = acc * rsn * (1.0f / CC);   // summary_avg_score[b]
    }
    __syncthreads();

    // ---- Pass B: inner score (rows reread from L2, S in registers) ----
    float4 sreg[8];
    #pragma unroll
    for (int i = 0; i < 8; i++) sreg[i] = Spriv[0][i * 32 + l];

    for (int r = w; r < CC; r += NWARPS) {
        const float4* rowp = cb + (size_t)r * (DD / 4);
        float dot = 0.f;
        #pragma unroll
        for (int i = 0; i < 8; i++) {
            float4 a = rowp[i * 32 + l];
            float4 s = sreg[i];
            dot = fmaf(a.x, s.x, dot); dot = fmaf(a.y, s.y, dot);
            dot = fmaf(a.z, s.z, dot); dot = fmaf(a.w, s.w, dot);
        }
        #pragma unroll
        for (int o = 16; o; o >>= 1)
            dot += __shfl_xor_sync(0xffffffffu, dot, o);
        if (l == 0) {
            // chat_r · S includes the self term (==1 up to fp32 rounding)
            out[BB * CC + b * CC + r] = (dot * rcn_s[r] - 1.0f) * (1.0f / (CC - 1));
        }
    }
}

extern "C" void kernel_launch(void* const* d_in, const int* in_sizes, int n_in,
                              void* d_out, int out_size) {
    const float* doc  = (const float*)d_in[0];   // [B, D]
    const float* summ = (const float*)d_in[1];   // [B, D]
    const float* cand = (const float*)d_in[2];   // [B, C, D]
    float* out = (float*)d_out;                  // [B*C | B*C | B | B]
    (void)in_sizes; (void)n_in; (void)out_size;

    reranker_kernel<<<BB, 256>>>(doc, summ, cand, out);
}